// round 1
// baseline (speedup 1.0000x reference)
#include <cuda_runtime.h>
#include <cuda_bf16.h>
#include <cstdint>

#define N_Q 4096
#define NTHREADS 1024
#define EVAL_PT_SCORE 0.05f
#define D2_THRESH 25.0f   // 5.0^2

// -------- device scratch (no allocations allowed) --------
__device__ float g_x[N_Q];
__device__ float g_y[N_Q];
__device__ float g_sc[2][N_Q];   // [0]=end scores, [1]=junction scores

// -------- Kernel A: softmax + pixel scale + first 3 output channels --------
__global__ void prep_kernel(const float* __restrict__ logits,
                            const float* __restrict__ boxes,
                            const float* __restrict__ ts,
                            float* __restrict__ out) {
    int i = blockIdx.x * blockDim.x + threadIdx.x;
    if (i >= N_Q) return;
    float l0 = logits[3 * i + 0];
    float l1 = logits[3 * i + 1];
    float l2 = logits[3 * i + 2];
    float m = fmaxf(l0, fmaxf(l1, l2));
    float e0 = expf(l0 - m);
    float e1 = expf(l1 - m);
    float e2 = expf(l2 - m);
    float inv = 1.0f / (e0 + e1 + e2);
    float p0 = e0 * inv, p1 = e1 * inv, p2 = e2 * inv;

    float x = boxes[2 * i + 0] * ts[0];
    float y = boxes[2 * i + 1] * ts[1];

    out[5 * i + 0] = 1.0f - p2;  // tgt score
    out[5 * i + 1] = x;
    out[5 * i + 2] = y;

    g_x[i] = x;
    g_y[i] = y;
    g_sc[0][i] = p0;
    g_sc[1][i] = p1;
}

// -------- shared-memory layout for NMS kernel --------
// u64  skey [4096]   32768   keys by ORIGINAL index (rank comparisons)
// u64  ssort[4096]   32768   sort workspace
// f32  sx   [4096]   16384
// f32  sy   [4096]   16384
// int  cstart[4097]  16388   cell start offsets (exclusive scan)
// int  ccur [4096]   16384   scatter cursors
// int  scanbuf[1024]  4096
// u16  cpt  [4096]    8192   point ids sorted by cell
// u16  scell[4096]    8192   cell id per point
// u8   stat [4096]    4096   0=unresolved 1=retained 2=not-retained
#define SMEM_BYTES (32768 + 32768 + 16384 + 16384 + 16388 + 16384 + 4096 + 8192 + 8192 + 4096)

__global__ void __launch_bounds__(NTHREADS, 1)
nms_kernel(float* __restrict__ out) {
    const int cls = blockIdx.x;   // 0 = end, 1 = junction
    const int tid = threadIdx.x;

    extern __shared__ unsigned char sm[];
    unsigned long long* skey  = (unsigned long long*)sm;
    unsigned long long* ssort = skey + N_Q;
    float* sx = (float*)(ssort + N_Q);
    float* sy = sx + N_Q;
    int* cstart = (int*)(sy + N_Q);      // 4097 ints
    int* ccur = cstart + (N_Q + 1);
    int* scanbuf = ccur + N_Q;           // 1024 ints
    unsigned short* cpt   = (unsigned short*)(scanbuf + NTHREADS);
    unsigned short* scell = cpt + N_Q;
    unsigned char* stat   = (unsigned char*)(scell + N_Q);
    __shared__ int s_unres;

    // ---- load + build keys + cell ids ----
    for (int i = tid; i < N_Q; i += NTHREADS) {
        float x = g_x[i], y = g_y[i];
        float s = g_sc[cls][i];
        sx[i] = x; sy[i] = y;
        bool valid = (s >= EVAL_PT_SCORE);
        unsigned int fb = __float_as_uint(s);   // s in (0,1): monotone as uint
        unsigned long long key = valid
            ? ((((unsigned long long)fb) << 32) | (unsigned int)(N_Q - 1 - i))
            : (unsigned long long)(unsigned int)(N_Q - 1 - i);
        skey[i] = key;
        ssort[i] = key;
        stat[i] = valid ? (unsigned char)0 : (unsigned char)2;
        int cx = min(63, max(0, (int)(x * 0.125f)));
        int cy = min(63, max(0, (int)(y * 0.125f)));
        scell[i] = (unsigned short)(cy * 64 + cx);
    }
    for (int c = tid; c < N_Q + 1; c += NTHREADS) cstart[c] = 0;
    __syncthreads();

    // ---- histogram ----
    for (int i = tid; i < N_Q; i += NTHREADS) atomicAdd(&cstart[scell[i]], 1);
    __syncthreads();

    // ---- exclusive scan over 4096 cells (4 cells/thread + block scan) ----
    int c0 = cstart[4 * tid + 0];
    int c1 = cstart[4 * tid + 1];
    int c2 = cstart[4 * tid + 2];
    int c3 = cstart[4 * tid + 3];
    int lsum = c0 + c1 + c2 + c3;
    scanbuf[tid] = lsum;
    __syncthreads();
    for (int off = 1; off < NTHREADS; off <<= 1) {
        int v = (tid >= off) ? scanbuf[tid - off] : 0;
        __syncthreads();
        scanbuf[tid] += v;
        __syncthreads();
    }
    int base = (tid == 0) ? 0 : scanbuf[tid - 1];
    cstart[4 * tid + 0] = base;
    cstart[4 * tid + 1] = base + c0;
    cstart[4 * tid + 2] = base + c0 + c1;
    cstart[4 * tid + 3] = base + c0 + c1 + c2;
    ccur[4 * tid + 0] = base;
    ccur[4 * tid + 1] = base + c0;
    ccur[4 * tid + 2] = base + c0 + c1;
    ccur[4 * tid + 3] = base + c0 + c1 + c2;
    if (tid == NTHREADS - 1) cstart[N_Q] = base + lsum;
    __syncthreads();

    // ---- scatter point ids by cell ----
    for (int i = tid; i < N_Q; i += NTHREADS) {
        int pos = atomicAdd(&ccur[scell[i]], 1);
        cpt[pos] = (unsigned short)i;
    }
    __syncthreads();

    // ---- greedy-NMS fixed point over the rank DAG ----
    // retained[j] <=> valid[j] and no retained higher-key point within dist<5.
    while (true) {
        __syncthreads();                 // protect re-zero vs previous round's read
        if (tid == 0) s_unres = 0;
        __syncthreads();
        int local_unres = 0;
        for (int i = tid; i < N_Q; i += NTHREADS) {
            if (stat[i] != 0) continue;
            unsigned long long kj = skey[i];
            float xj = sx[i], yj = sy[i];
            int cell = scell[i];
            int cx = cell & 63, cy = cell >> 6;
            bool sup = false, allres = true;
            for (int dy = -1; dy <= 1 && !sup; dy++) {
                int yy = cy + dy;
                if (yy < 0 || yy > 63) continue;
                for (int dx = -1; dx <= 1 && !sup; dx++) {
                    int xx = cx + dx;
                    if (xx < 0 || xx > 63) continue;
                    int c = yy * 64 + xx;
                    int e = cstart[c + 1];
                    for (int p = cstart[c]; p < e; p++) {
                        int k2 = cpt[p];
                        unsigned long long ki = skey[k2];
                        if (ki <= kj) continue;       // only higher-ranked (also skips invalid & self)
                        float ddx = sx[k2] - xj;
                        float ddy = sy[k2] - yj;
                        float d2 = ddx * ddx + ddy * ddy;
                        if (d2 < D2_THRESH) {
                            unsigned char st = stat[k2];
                            if (st == 1) { sup = true; break; }
                            if (st == 0) allres = false;
                        }
                    }
                }
            }
            if (sup)          stat[i] = 2;
            else if (allres)  stat[i] = 1;
            else              local_unres++;
        }
        if (local_unres) atomicAdd(&s_unres, local_unres);
        __syncthreads();
        if (s_unres == 0) break;         // uniform across block
    }

    // ---- bitonic sort of keys, descending (matches stable argsort(-score)) ----
    for (int k = 2; k <= N_Q; k <<= 1) {
        for (int j = k >> 1; j > 0; j >>= 1) {
            __syncthreads();
            for (int i = tid; i < N_Q; i += NTHREADS) {
                int ixj = i ^ j;
                if (ixj > i) {
                    unsigned long long a = ssort[i];
                    unsigned long long b = ssort[ixj];
                    bool up = ((i & k) == 0);           // descending block
                    if ((a < b) == up) {
                        ssort[i] = b;
                        ssort[ixj] = a;
                    }
                }
            }
        }
    }
    __syncthreads();

    // ---- write sorted-slot NMS scores ----
    for (int n = tid; n < N_Q; n += NTHREADS) {
        unsigned long long key = ssort[n];
        unsigned int hi = (unsigned int)(key >> 32);
        float val = 0.0f;
        if (hi) {
            int idx = N_Q - 1 - (int)(unsigned int)(key & 0xFFFFFFFFull);
            if (stat[idx] == 1) val = __uint_as_float(hi);  // exact score from key
        }
        out[5 * n + 3 + cls] = val;
    }
}

extern "C" void kernel_launch(void* const* d_in, const int* in_sizes, int n_in,
                              void* d_out, int out_size) {
    const float* logits = (const float*)d_in[0];   // [1,4096,3]
    const float* boxes  = (const float*)d_in[1];   // [1,4096,2]
    // d_in[2] = pred_gids (unused by reference)
    const float* ts     = (const float*)d_in[3];   // [1,2] = (w,h)
    float* out = (float*)d_out;                    // [1,4096,5]

    prep_kernel<<<N_Q / 256, 256>>>(logits, boxes, ts, out);

    cudaFuncSetAttribute(nms_kernel,
                         cudaFuncAttributeMaxDynamicSharedMemorySize, SMEM_BYTES);
    nms_kernel<<<2, NTHREADS, SMEM_BYTES>>>(out);
}

// round 2
// speedup vs baseline: 1.4853x; 1.4853x over previous
#include <cuda_runtime.h>
#include <cuda_bf16.h>
#include <cstdint>

#define N_Q 4096
#define NTHREADS 1024
#define EVAL_PT_SCORE 0.05f
#define D2_THRESH 25.0f   // 5.0^2

// -------- device scratch (no allocations allowed) --------
__device__ float g_x[N_Q];
__device__ float g_y[N_Q];
__device__ float g_sc[2][N_Q];   // [0]=end scores, [1]=junction scores

// -------- Kernel A: softmax + pixel scale + output channels 0-2, zero 3-4 ----
__global__ void prep_kernel(const float* __restrict__ logits,
                            const float* __restrict__ boxes,
                            const float* __restrict__ ts,
                            float* __restrict__ out) {
    int i = blockIdx.x * blockDim.x + threadIdx.x;
    if (i >= N_Q) return;
    float l0 = logits[3 * i + 0];
    float l1 = logits[3 * i + 1];
    float l2 = logits[3 * i + 2];
    float m = fmaxf(l0, fmaxf(l1, l2));
    float e0 = expf(l0 - m);
    float e1 = expf(l1 - m);
    float e2 = expf(l2 - m);
    float inv = 1.0f / (e0 + e1 + e2);
    float p0 = e0 * inv, p1 = e1 * inv, p2 = e2 * inv;

    float x = boxes[2 * i + 0] * ts[0];
    float y = boxes[2 * i + 1] * ts[1];

    out[5 * i + 0] = 1.0f - p2;  // tgt score
    out[5 * i + 1] = x;
    out[5 * i + 2] = y;
    out[5 * i + 3] = 0.0f;       // NMS channels default (suppressed / invalid slots)
    out[5 * i + 4] = 0.0f;

    g_x[i] = x;
    g_y[i] = y;
    g_sc[0][i] = p0;
    g_sc[1][i] = p1;
}

// -------- shared-memory layout for NMS+rank kernel --------
// u64  skey [4096]    32768   keys by ORIGINAL index
// f32  sx,sy[4096]    32768
// int  cstart[4097]   16388   spatial cells CSR
// int  ccur [4096]    16384
// int  bstart[4097]   16388   score-value buckets CSR (valid points only)
// int  bcur [4096]    16384
// int  scanbuf[1024]   4096
// u16  cpt  [4096]     8192
// u16  scell[4096]     8192
// u16  sbuck[4096]     8192
// u16  bpt  [4096]     8192
// u8   stat [4096]     4096   0=unresolved 1=retained 2=not-retained
#define SMEM_BYTES (32768 + 32768 + 16388 + 16384 + 16388 + 16384 + 4096 \
                    + 8192 + 8192 + 8192 + 8192 + 4096)

__global__ void __launch_bounds__(NTHREADS, 1)
nms_kernel(float* __restrict__ out) {
    const int cls = blockIdx.x;   // 0 = end, 1 = junction
    const int tid = threadIdx.x;

    extern __shared__ unsigned char sm[];
    unsigned long long* skey = (unsigned long long*)sm;
    float* sx = (float*)(skey + N_Q);
    float* sy = sx + N_Q;
    int* cstart = (int*)(sy + N_Q);      // 4097 ints
    int* ccur = cstart + (N_Q + 1);
    int* bstart = ccur + N_Q;            // 4097 ints
    int* bcur = bstart + (N_Q + 1);
    int* scanbuf = bcur + N_Q;           // 1024 ints
    unsigned short* cpt   = (unsigned short*)(scanbuf + NTHREADS);
    unsigned short* scell = cpt + N_Q;
    unsigned short* sbuck = scell + N_Q;
    unsigned short* bpt   = sbuck + N_Q;
    unsigned char* stat   = (unsigned char*)(bpt + N_Q);
    __shared__ int s_unres;

    // ---- load + build keys + cell ids + bucket ids ----
    for (int i = tid; i < N_Q; i += NTHREADS) {
        float x = g_x[i], y = g_y[i];
        float s = g_sc[cls][i];
        sx[i] = x; sy[i] = y;
        bool valid = (s >= EVAL_PT_SCORE);
        unsigned int fb = __float_as_uint(s);   // s in (0,1): monotone as uint
        unsigned long long key = valid
            ? ((((unsigned long long)fb) << 32) | (unsigned int)(N_Q - 1 - i))
            : (unsigned long long)(unsigned int)(N_Q - 1 - i);
        skey[i] = key;
        stat[i] = valid ? (unsigned char)0 : (unsigned char)2;
        int cx = min(63, max(0, (int)(x * 0.125f)));
        int cy = min(63, max(0, (int)(y * 0.125f)));
        scell[i] = (unsigned short)(cy * 64 + cx);
        sbuck[i] = (unsigned short)min(4095, (int)(s * 4096.0f));   // monotone in s
    }
    for (int c = tid; c < N_Q + 1; c += NTHREADS) { cstart[c] = 0; bstart[c] = 0; }
    __syncthreads();

    // ---- histograms (cells: all points; buckets: valid only) ----
    for (int i = tid; i < N_Q; i += NTHREADS) {
        atomicAdd(&cstart[scell[i]], 1);
        if (stat[i] == 0) atomicAdd(&bstart[sbuck[i]], 1);
    }
    __syncthreads();

    // ---- exclusive scan over cells ----
    {
        int c0 = cstart[4 * tid + 0];
        int c1 = cstart[4 * tid + 1];
        int c2 = cstart[4 * tid + 2];
        int c3 = cstart[4 * tid + 3];
        int lsum = c0 + c1 + c2 + c3;
        scanbuf[tid] = lsum;
        __syncthreads();
        for (int off = 1; off < NTHREADS; off <<= 1) {
            int v = (tid >= off) ? scanbuf[tid - off] : 0;
            __syncthreads();
            scanbuf[tid] += v;
            __syncthreads();
        }
        int base = (tid == 0) ? 0 : scanbuf[tid - 1];
        cstart[4 * tid + 0] = base;
        cstart[4 * tid + 1] = base + c0;
        cstart[4 * tid + 2] = base + c0 + c1;
        cstart[4 * tid + 3] = base + c0 + c1 + c2;
        ccur[4 * tid + 0] = base;
        ccur[4 * tid + 1] = base + c0;
        ccur[4 * tid + 2] = base + c0 + c1;
        ccur[4 * tid + 3] = base + c0 + c1 + c2;
        if (tid == NTHREADS - 1) cstart[N_Q] = base + lsum;
    }
    __syncthreads();

    // ---- exclusive scan over score buckets ----
    {
        int c0 = bstart[4 * tid + 0];
        int c1 = bstart[4 * tid + 1];
        int c2 = bstart[4 * tid + 2];
        int c3 = bstart[4 * tid + 3];
        int lsum = c0 + c1 + c2 + c3;
        scanbuf[tid] = lsum;
        __syncthreads();
        for (int off = 1; off < NTHREADS; off <<= 1) {
            int v = (tid >= off) ? scanbuf[tid - off] : 0;
            __syncthreads();
            scanbuf[tid] += v;
            __syncthreads();
        }
        int base = (tid == 0) ? 0 : scanbuf[tid - 1];
        bstart[4 * tid + 0] = base;
        bstart[4 * tid + 1] = base + c0;
        bstart[4 * tid + 2] = base + c0 + c1;
        bstart[4 * tid + 3] = base + c0 + c1 + c2;
        bcur[4 * tid + 0] = base;
        bcur[4 * tid + 1] = base + c0;
        bcur[4 * tid + 2] = base + c0 + c1;
        bcur[4 * tid + 3] = base + c0 + c1 + c2;
        if (tid == NTHREADS - 1) bstart[N_Q] = base + lsum;   // = Nvalid
    }
    __syncthreads();

    // ---- scatter point ids (cells; buckets for valid points) ----
    for (int i = tid; i < N_Q; i += NTHREADS) {
        int pos = atomicAdd(&ccur[scell[i]], 1);
        cpt[pos] = (unsigned short)i;
        if (stat[i] == 0) {
            int bp = atomicAdd(&bcur[sbuck[i]], 1);
            bpt[bp] = (unsigned short)i;
        }
    }
    __syncthreads();

    // ---- greedy-NMS fixed point over the rank DAG ----
    // retained[j] <=> valid[j] and no retained higher-key point within dist<5.
    while (true) {
        __syncthreads();
        if (tid == 0) s_unres = 0;
        __syncthreads();
        int local_unres = 0;
        for (int i = tid; i < N_Q; i += NTHREADS) {
            if (stat[i] != 0) continue;
            unsigned long long kj = skey[i];
            float xj = sx[i], yj = sy[i];
            int cell = scell[i];
            int cx = cell & 63, cy = cell >> 6;
            bool sup = false, allres = true;
            for (int dy = -1; dy <= 1 && !sup; dy++) {
                int yy = cy + dy;
                if (yy < 0 || yy > 63) continue;
                for (int dx = -1; dx <= 1 && !sup; dx++) {
                    int xx = cx + dx;
                    if (xx < 0 || xx > 63) continue;
                    int c = yy * 64 + xx;
                    int e = cstart[c + 1];
                    for (int p = cstart[c]; p < e; p++) {
                        int k2 = cpt[p];
                        unsigned long long ki = skey[k2];
                        if (ki <= kj) continue;       // only higher-ranked
                        float ddx = sx[k2] - xj;
                        float ddy = sy[k2] - yj;
                        float d2 = ddx * ddx + ddy * ddy;
                        if (d2 < D2_THRESH) {
                            unsigned char st = stat[k2];
                            if (st == 1) { sup = true; break; }
                            if (st == 0) allres = false;
                        }
                    }
                }
            }
            if (sup)          stat[i] = 2;
            else if (allres)  stat[i] = 1;
            else              local_unres++;
        }
        if (local_unres) atomicAdd(&s_unres, local_unres);
        __syncthreads();
        if (s_unres == 0) break;         // uniform across block
    }

    // ---- rank retained points among valid (descending key) and scatter ----
    // rank = #{valid in higher buckets} + #{same-bucket mates with greater key}
    const int nvalid = bstart[N_Q];
    for (int i = tid; i < N_Q; i += NTHREADS) {
        if (stat[i] != 1) continue;      // only retained points produce nonzero
        unsigned long long kj = skey[i];
        int b = sbuck[i];
        int r = nvalid - bstart[b + 1];  // valid points in strictly higher buckets
        int e = bstart[b + 1];
        for (int p = bstart[b]; p < e; p++) {
            if (skey[bpt[p]] > kj) r++;
        }
        out[5 * r + 3 + cls] = __uint_as_float((unsigned int)(kj >> 32));
    }
}

extern "C" void kernel_launch(void* const* d_in, const int* in_sizes, int n_in,
                              void* d_out, int out_size) {
    const float* logits = (const float*)d_in[0];   // [1,4096,3]
    const float* boxes  = (const float*)d_in[1];   // [1,4096,2]
    // d_in[2] = pred_gids (unused by reference)
    const float* ts     = (const float*)d_in[3];   // [1,2] = (w,h)
    float* out = (float*)d_out;                    // [1,4096,5]

    prep_kernel<<<N_Q / 256, 256>>>(logits, boxes, ts, out);

    cudaFuncSetAttribute(nms_kernel,
                         cudaFuncAttributeMaxDynamicSharedMemorySize, SMEM_BYTES);
    nms_kernel<<<2, NTHREADS, SMEM_BYTES>>>(out);
}

// round 3
// speedup vs baseline: 2.6630x; 1.7929x over previous
#include <cuda_runtime.h>
#include <cuda_bf16.h>
#include <cstdint>

#define N_Q 4096
#define NTHREADS 1024
#define EVAL_PT_SCORE 0.05f
#define D2_THRESH 25.0f   // 5.0^2
#define NBR_CAP 6
#define OVF 255

// shared-memory layout (bytes):
// u64    ckey [4096]      32768   keys, CELL order
// float2 cxy  [4096]      32768   coords, CELL order
// int    cstart[4097]     16388   cell CSR
// int    ccur [4096]      16384
// int    bstart[4097]     16388   score-bucket CSR (valid points)
// int    bcur [4096]      16384
// int    warpsum[64]        256
// u16    ccell[4096]       8192   cell id per CELL-order point
// u16    bpt  [4096]       8192   bucket-sorted CELL-order positions
// u16    wl   [4096]       8192   worklist of unresolved positions
// u16    nbr  [4096*6]    49152   higher-ranked neighbor lists
// u8     stat [4096]       4096   0=unresolved 1=retained 2=not-retained
// u8     nbrcnt[4096]      4096   count or OVF
#define SMEM_BYTES (32768 + 32768 + 16388 + 16384 + 16388 + 16384 + 256 \
                    + 8192 + 8192 + 8192 + 49152 + 4096 + 4096)

__device__ __forceinline__ int warp_incl_scan(int v) {
    int lane = threadIdx.x & 31;
    #pragma unroll
    for (int o = 1; o < 32; o <<= 1) {
        int n = __shfl_up_sync(0xffffffffu, v, o);
        if (lane >= o) v += n;
    }
    return v;
}

__global__ void __launch_bounds__(NTHREADS, 1)
nms_kernel(const float* __restrict__ logits,
           const float* __restrict__ boxes,
           const float* __restrict__ ts,
           float* __restrict__ out) {
    const int cls = blockIdx.x;   // 0 = end, 1 = junction
    const int tid = threadIdx.x;
    const int lane = tid & 31;
    const int wid = tid >> 5;

    extern __shared__ unsigned char sm[];
    unsigned long long* ckey = (unsigned long long*)sm;
    float2* cxy = (float2*)(ckey + N_Q);
    int* cstart = (int*)(cxy + N_Q);        // 4097
    int* ccur   = cstart + (N_Q + 1);
    int* bstart = ccur + N_Q;               // 4097
    int* bcur   = bstart + (N_Q + 1);
    int* warpsum = bcur + N_Q;              // 64
    unsigned short* ccell = (unsigned short*)(warpsum + 64);
    unsigned short* bpt   = ccell + N_Q;
    unsigned short* wl    = bpt + N_Q;
    unsigned short* nbr   = wl + N_Q;       // 4096*NBR_CAP
    unsigned char* stat   = (unsigned char*)(nbr + N_Q * NBR_CAP);
    unsigned char* nbrcnt = stat + N_Q;
    __shared__ int s_unres, s_wl;

    const float tw = ts[0], th = ts[1];

    // ---- phase 1: per-thread block of 4 points, kept in registers ----
    float rx[4], ry[4];
    unsigned long long rkey[4];
    int rcell[4], rbuck[4];
    bool rvalid[4];
    #pragma unroll
    for (int k = 0; k < 4; k++) {
        int i = 4 * tid + k;
        float l0 = logits[3 * i + 0];
        float l1 = logits[3 * i + 1];
        float l2 = logits[3 * i + 2];
        float m = fmaxf(l0, fmaxf(l1, l2));
        float e0 = __expf(l0 - m) , e1 = __expf(l1 - m), e2 = __expf(l2 - m);
        // NOTE: use exact expf for bit-closeness to reference
        e0 = expf(l0 - m); e1 = expf(l1 - m); e2 = expf(l2 - m);
        float inv = 1.0f / (e0 + e1 + e2);
        float p0 = e0 * inv, p1 = e1 * inv, p2 = e2 * inv;
        float x = boxes[2 * i + 0] * tw;
        float y = boxes[2 * i + 1] * th;
        float s = (cls == 0) ? p0 : p1;
        rx[k] = x; ry[k] = y;
        bool valid = (s >= EVAL_PT_SCORE);
        rvalid[k] = valid;
        unsigned int fb = __float_as_uint(s);
        rkey[k] = valid
            ? ((((unsigned long long)fb) << 32) | (unsigned int)(N_Q - 1 - i))
            : (unsigned long long)(unsigned int)(N_Q - 1 - i);
        int cx = min(63, max(0, (int)(x * 0.125f)));
        int cy = min(63, max(0, (int)(y * 0.125f)));
        rcell[k] = cy * 64 + cx;
        rbuck[k] = min(4095, (int)(s * 4096.0f));
        // output: block 0 writes ch0-2 + zeroes ch3; block 1 zeroes ch4
        if (cls == 0) {
            out[5 * i + 0] = 1.0f - p2;
            out[5 * i + 1] = x;
            out[5 * i + 2] = y;
            out[5 * i + 3] = 0.0f;
        } else {
            out[5 * i + 4] = 0.0f;
        }
    }
    // zero histograms
    for (int c = tid; c < N_Q + 1; c += NTHREADS) { cstart[c] = 0; bstart[c] = 0; }
    if (tid == 0) s_wl = 0;
    __syncthreads();

    // ---- histograms ----
    #pragma unroll
    for (int k = 0; k < 4; k++) {
        atomicAdd(&cstart[rcell[k]], 1);
        if (rvalid[k]) atomicAdd(&bstart[rbuck[k]], 1);
    }
    __syncthreads();

    // ---- exclusive scans (warp-shuffle, 2 barriers each) ----
    {
        int h0 = cstart[4 * tid], h1 = cstart[4 * tid + 1];
        int h2 = cstart[4 * tid + 2], h3 = cstart[4 * tid + 3];
        int g0 = bstart[4 * tid], g1 = bstart[4 * tid + 1];
        int g2 = bstart[4 * tid + 2], g3 = bstart[4 * tid + 3];
        int lc = h0 + h1 + h2 + h3;
        int lb = g0 + g1 + g2 + g3;
        int ic = warp_incl_scan(lc);
        int ib = warp_incl_scan(lb);
        if (lane == 31) { warpsum[wid] = ic; warpsum[32 + wid] = ib; }
        __syncthreads();
        if (wid == 0) {
            int wc = warpsum[lane];
            int wb = warpsum[32 + lane];
            warpsum[lane] = warp_incl_scan(wc);
            warpsum[32 + lane] = warp_incl_scan(wb);
        }
        __syncthreads();
        int basec = ic - lc + (wid ? warpsum[wid - 1] : 0);
        int baseb = ib - lb + (wid ? warpsum[32 + wid - 1] : 0);
        cstart[4 * tid] = basec;          ccur[4 * tid] = basec;
        cstart[4 * tid + 1] = basec + h0; ccur[4 * tid + 1] = basec + h0;
        cstart[4 * tid + 2] = basec + h0 + h1; ccur[4 * tid + 2] = basec + h0 + h1;
        cstart[4 * tid + 3] = basec + h0 + h1 + h2; ccur[4 * tid + 3] = basec + h0 + h1 + h2;
        bstart[4 * tid] = baseb;          bcur[4 * tid] = baseb;
        bstart[4 * tid + 1] = baseb + g0; bcur[4 * tid + 1] = baseb + g0;
        bstart[4 * tid + 2] = baseb + g0 + g1; bcur[4 * tid + 2] = baseb + g0 + g1;
        bstart[4 * tid + 3] = baseb + g0 + g1 + g2; bcur[4 * tid + 3] = baseb + g0 + g1 + g2;
        if (tid == NTHREADS - 1) { cstart[N_Q] = basec + lc; bstart[N_Q] = baseb + lb; }
    }
    __syncthreads();

    // ---- scatter into cell order; bucket list stores cell-order positions ----
    #pragma unroll
    for (int k = 0; k < 4; k++) {
        int pos = atomicAdd(&ccur[rcell[k]], 1);
        ckey[pos] = rkey[k];
        cxy[pos] = make_float2(rx[k], ry[k]);
        ccell[pos] = (unsigned short)rcell[k];
        stat[pos] = rvalid[k] ? (unsigned char)0 : (unsigned char)2;
        if (rvalid[k]) {
            int bp = atomicAdd(&bcur[rbuck[k]], 1);
            bpt[bp] = (unsigned short)pos;
        }
    }
    __syncthreads();

    // ---- edge build: higher-ranked valid within-thresh neighbors, capped ----
    for (int p = tid; p < N_Q; p += NTHREADS) {
        if (stat[p] != 0) continue;           // invalid
        unsigned long long kj = ckey[p];
        float2 pj = cxy[p];
        int cell = ccell[p];
        int cx = cell & 63, cy = cell >> 6;
        int x0 = max(cx - 1, 0), x1 = min(cx + 1, 63);
        int y0 = max(cy - 1, 0), y1 = min(cy + 1, 63);
        int cnt = 0; bool ovf = false;
        for (int yy = y0; yy <= y1; yy++) {
            int rs = cstart[yy * 64 + x0];
            int re = cstart[yy * 64 + x1 + 1];
            for (int q = rs; q < re; q++) {
                unsigned long long ki = ckey[q];
                if (ki <= kj) continue;       // lower-ranked, invalid, or self
                float2 pi = cxy[q];
                float dx = pi.x - pj.x, dy = pi.y - pj.y;
                if (dx * dx + dy * dy < D2_THRESH) {
                    if (cnt < NBR_CAP) nbr[p * NBR_CAP + cnt] = (unsigned short)q;
                    cnt++;
                }
            }
        }
        if (cnt > NBR_CAP) { ovf = true; }
        if (cnt == 0) {
            stat[p] = 1;                      // no higher-ranked neighbor: retained
        } else {
            nbrcnt[p] = ovf ? (unsigned char)OVF : (unsigned char)cnt;
            int w = atomicAdd(&s_wl, 1);
            wl[w] = (unsigned short)p;
        }
    }
    __syncthreads();
    const int nwl = s_wl;

    // ---- fixed-point rounds over compact worklist ----
    while (true) {
        __syncthreads();
        if (tid == 0) s_unres = 0;
        __syncthreads();
        int local_unres = 0;
        for (int w = tid; w < nwl; w += NTHREADS) {
            int p = wl[w];
            if (stat[p] != 0) continue;
            int c = nbrcnt[p];
            bool sup = false, pend = false;
            if (c != OVF) {
                #pragma unroll 1
                for (int k = 0; k < c; k++) {
                    unsigned char st = stat[nbr[p * NBR_CAP + k]];
                    if (st == 1) { sup = true; break; }
                    if (st == 0) pend = true;
                }
            } else {
                // rare overflow: rescan cell ranges
                unsigned long long kj = ckey[p];
                float2 pj = cxy[p];
                int cell = ccell[p];
                int cx = cell & 63, cy = cell >> 6;
                int x0 = max(cx - 1, 0), x1 = min(cx + 1, 63);
                int y0 = max(cy - 1, 0), y1 = min(cy + 1, 63);
                for (int yy = y0; yy <= y1 && !sup; yy++) {
                    int rs = cstart[yy * 64 + x0];
                    int re = cstart[yy * 64 + x1 + 1];
                    for (int q = rs; q < re; q++) {
                        unsigned long long ki = ckey[q];
                        if (ki <= kj) continue;
                        float2 pi = cxy[q];
                        float dx = pi.x - pj.x, dy = pi.y - pj.y;
                        if (dx * dx + dy * dy < D2_THRESH) {
                            unsigned char st = stat[q];
                            if (st == 1) { sup = true; break; }
                            if (st == 0) pend = true;
                        }
                    }
                }
            }
            if (sup)       stat[p] = 2;
            else if (!pend) stat[p] = 1;
            else           local_unres++;
        }
        if (local_unres) atomicAdd(&s_unres, local_unres);
        __syncthreads();
        if (s_unres == 0) break;
    }

    // ---- rank retained among valid (descending key), scatter to output ----
    const int nvalid = bstart[N_Q];
    for (int p = tid; p < N_Q; p += NTHREADS) {
        if (stat[p] != 1) continue;
        unsigned long long kj = ckey[p];
        float s = __uint_as_float((unsigned int)(kj >> 32));
        int b = min(4095, (int)(s * 4096.0f));
        int r = nvalid - bstart[b + 1];
        int e = bstart[b + 1];
        for (int q = bstart[b]; q < e; q++) {
            if (ckey[bpt[q]] > kj) r++;
        }
        out[5 * r + 3 + cls] = s;
    }
}

extern "C" void kernel_launch(void* const* d_in, const int* in_sizes, int n_in,
                              void* d_out, int out_size) {
    const float* logits = (const float*)d_in[0];   // [1,4096,3]
    const float* boxes  = (const float*)d_in[1];   // [1,4096,2]
    // d_in[2] = pred_gids (unused by reference)
    const float* ts     = (const float*)d_in[3];   // [1,2] = (w,h)
    float* out = (float*)d_out;                    // [1,4096,5]

    cudaFuncSetAttribute(nms_kernel,
                         cudaFuncAttributeMaxDynamicSharedMemorySize, SMEM_BYTES);
    nms_kernel<<<2, NTHREADS, SMEM_BYTES>>>(logits, boxes, ts, out);
}

// round 4
// speedup vs baseline: 3.4435x; 1.2931x over previous
#include <cuda_runtime.h>
#include <cstdint>

#define N_Q 4096
#define QTR 1024
#define NTHREADS 1024
#define CLUSTER 4
#define EVAL_PT_SCORE 0.05f
#define D2_THRESH 25.0f   // 5.0^2
#define NBR_CAP 6
#define OVF 255

// smem: ckey u64[4096] | cxy f2[4096] | ixy f2[4096] | iscore f32[4096]
//       cstart[4097] ccur[4096] bstart[4097] bcur[4096] warpsum[64]
//       cidx u16[4096] ccell u16[4096] bpt u16[4096] wl u16[1024] nbr u16[6144]
//       stat u8[4096] nbrcnt u8[1024]   => 224,520 bytes
#define SMEM_BYTES 224520

__device__ __forceinline__ uint32_t smem_u32(const void* p) {
    uint32_t a;
    asm("{ .reg .u64 t; cvta.to.shared.u64 t, %1; cvt.u32.u64 %0, t; }"
        : "=r"(a) : "l"(p));
    return a;
}
__device__ __forceinline__ uint32_t mapa_rank(uint32_t addr, uint32_t r) {
    uint32_t o;
    asm("mapa.shared::cluster.u32 %0, %1, %2;" : "=r"(o) : "r"(addr), "r"(r));
    return o;
}
__device__ __forceinline__ void st_cl_u32(uint32_t addr, uint32_t v) {
    asm volatile("st.shared::cluster.u32 [%0], %1;" :: "r"(addr), "r"(v) : "memory");
}
__device__ __forceinline__ void st_cl_f32(uint32_t addr, float v) {
    asm volatile("st.shared::cluster.f32 [%0], %1;" :: "r"(addr), "f"(v) : "memory");
}
__device__ __forceinline__ void st_cl_v2f32(uint32_t addr, float a, float b) {
    asm volatile("st.shared::cluster.v2.f32 [%0], {%1,%2};"
                 :: "r"(addr), "f"(a), "f"(b) : "memory");
}
__device__ __forceinline__ uint32_t ctarank() {
    uint32_t r; asm("mov.u32 %0, %%cluster_ctarank;" : "=r"(r)); return r;
}
#define CLUSTER_SYNC() do { \
    asm volatile("barrier.cluster.arrive.aligned;" ::: "memory"); \
    asm volatile("barrier.cluster.wait.aligned;" ::: "memory"); } while (0)

__device__ __forceinline__ int warp_incl_scan(int v) {
    int lane = threadIdx.x & 31;
    #pragma unroll
    for (int o = 1; o < 32; o <<= 1) {
        int n = __shfl_up_sync(0xffffffffu, v, o);
        if (lane >= o) v += n;
    }
    return v;
}

__device__ __forceinline__ unsigned long long mk_key(float s, int i) {
    bool valid = (s >= EVAL_PT_SCORE);
    unsigned int fb = __float_as_uint(s);
    return valid
        ? ((((unsigned long long)fb) << 32) | (unsigned int)(N_Q - 1 - i))
        : (unsigned long long)(unsigned int)(N_Q - 1 - i);
}

__global__ void __launch_bounds__(NTHREADS, 1) __cluster_dims__(CLUSTER, 1, 1)
nms_kernel(const float* __restrict__ logits,
           const float* __restrict__ boxes,
           const float* __restrict__ ts,
           float* __restrict__ out) {
    const int cls = blockIdx.x / CLUSTER;   // 0 = end, 1 = junction
    const int rank = (int)ctarank();
    const int tid = threadIdx.x;
    const int lane = tid & 31;
    const int wid = tid >> 5;

    extern __shared__ unsigned char sm[];
    unsigned long long* ckey = (unsigned long long*)sm;
    float2* cxy = (float2*)(ckey + N_Q);
    float2* ixy = cxy + N_Q;
    float* iscore = (float*)(ixy + N_Q);
    int* cstart = (int*)(iscore + N_Q);      // 4097
    int* ccur   = cstart + (N_Q + 1);
    int* bstart = ccur + N_Q;                // 4097
    int* bcur   = bstart + (N_Q + 1);
    int* warpsum = bcur + N_Q;               // 64
    unsigned short* cidx  = (unsigned short*)(warpsum + 64);
    unsigned short* ccell = cidx + N_Q;
    unsigned short* bpt   = ccell + N_Q;
    unsigned short* wl    = bpt + N_Q;       // 1024
    unsigned short* nbr   = wl + QTR;        // 1024*NBR_CAP
    unsigned char* stat   = (unsigned char*)(nbr + QTR * NBR_CAP);
    unsigned char* nbrcnt = stat + N_Q;
    __shared__ int s_cnt[CLUSTER];
    __shared__ int s_my, s_wl;

    const float tw = ts[0], th = ts[1];

    // ---------- phase A: my quarter's softmax + share (s,x,y) to peers ----------
    {
        int i = rank * QTR + tid;
        float l0 = logits[3 * i + 0];
        float l1 = logits[3 * i + 1];
        float l2 = logits[3 * i + 2];
        float m = fmaxf(l0, fmaxf(l1, l2));
        float e0 = expf(l0 - m), e1 = expf(l1 - m), e2 = expf(l2 - m);
        float inv = 1.0f / (e0 + e1 + e2);
        float p0 = e0 * inv, p1 = e1 * inv, p2 = e2 * inv;
        float x = boxes[2 * i + 0] * tw;
        float y = boxes[2 * i + 1] * th;
        float s = (cls == 0) ? p0 : p1;
        iscore[i] = s;
        ixy[i] = make_float2(x, y);
        uint32_t a_is = smem_u32(&iscore[i]);
        uint32_t a_xy = smem_u32(&ixy[i]);
        #pragma unroll
        for (int r = 0; r < CLUSTER; r++) {
            if (r == rank) continue;
            st_cl_f32(mapa_rank(a_is, r), s);
            st_cl_v2f32(mapa_rank(a_xy, r), x, y);
        }
        if (cls == 0) {
            out[5 * i + 0] = 1.0f - p2;
            out[5 * i + 1] = x;
            out[5 * i + 2] = y;
            out[5 * i + 3] = 0.0f;
        } else {
            out[5 * i + 4] = 0.0f;
        }
    }
    for (int c = tid; c < N_Q + 1; c += NTHREADS) { cstart[c] = 0; bstart[c] = 0; }
    if (tid == 0) s_wl = 0;
    CLUSTER_SYNC();   // peers' (s,x,y) visible; also acts as block barrier

    // ---------- histograms over all 4096 (duplicated per CTA) ----------
    int hc[4], hb[4];
    #pragma unroll
    for (int k = 0; k < 4; k++) {
        int j = 4 * tid + k;
        float s = iscore[j];
        float2 p = ixy[j];
        int cx = min(63, max(0, (int)(p.x * 0.125f)));
        int cy = min(63, max(0, (int)(p.y * 0.125f)));
        hc[k] = cy * 64 + cx;
        hb[k] = min(4095, (int)(s * 4096.0f));
        bool valid = (s >= EVAL_PT_SCORE);
        stat[j] = valid ? (unsigned char)0 : (unsigned char)2;
        atomicAdd(&cstart[hc[k]], 1);
        if (valid) atomicAdd(&bstart[hb[k]], 1);
    }
    __syncthreads();

    // ---------- exclusive scans (warp shuffle) ----------
    {
        int h0 = cstart[4 * tid], h1 = cstart[4 * tid + 1];
        int h2 = cstart[4 * tid + 2], h3 = cstart[4 * tid + 3];
        int g0 = bstart[4 * tid], g1 = bstart[4 * tid + 1];
        int g2 = bstart[4 * tid + 2], g3 = bstart[4 * tid + 3];
        int lc = h0 + h1 + h2 + h3;
        int lb = g0 + g1 + g2 + g3;
        int ic = warp_incl_scan(lc);
        int ib = warp_incl_scan(lb);
        if (lane == 31) { warpsum[wid] = ic; warpsum[32 + wid] = ib; }
        __syncthreads();
        if (wid == 0) {
            int wc = warpsum[lane];
            int wb = warpsum[32 + lane];
            warpsum[lane] = warp_incl_scan(wc);
            warpsum[32 + lane] = warp_incl_scan(wb);
        }
        __syncthreads();
        int basec = ic - lc + (wid ? warpsum[wid - 1] : 0);
        int baseb = ib - lb + (wid ? warpsum[32 + wid - 1] : 0);
        cstart[4 * tid] = basec;                     ccur[4 * tid] = basec;
        cstart[4 * tid + 1] = basec + h0;            ccur[4 * tid + 1] = basec + h0;
        cstart[4 * tid + 2] = basec + h0 + h1;       ccur[4 * tid + 2] = basec + h0 + h1;
        cstart[4 * tid + 3] = basec + h0 + h1 + h2;  ccur[4 * tid + 3] = basec + h0 + h1 + h2;
        bstart[4 * tid] = baseb;                     bcur[4 * tid] = baseb;
        bstart[4 * tid + 1] = baseb + g0;            bcur[4 * tid + 1] = baseb + g0;
        bstart[4 * tid + 2] = baseb + g0 + g1;       bcur[4 * tid + 2] = baseb + g0 + g1;
        bstart[4 * tid + 3] = baseb + g0 + g1 + g2;  bcur[4 * tid + 3] = baseb + g0 + g1 + g2;
        if (tid == NTHREADS - 1) { cstart[N_Q] = basec + lc; bstart[N_Q] = baseb + lb; }
    }
    __syncthreads();

    // ---------- scatter into cell order; bucket list stores ORIGINAL idx ----------
    #pragma unroll
    for (int k = 0; k < 4; k++) {
        int j = 4 * tid + k;
        float s = iscore[j];
        float2 p = ixy[j];
        int pos = atomicAdd(&ccur[hc[k]], 1);
        ckey[pos] = mk_key(s, j);
        cxy[pos] = p;
        cidx[pos] = (unsigned short)j;
        ccell[pos] = (unsigned short)hc[k];
        if (s >= EVAL_PT_SCORE) {
            int bp = atomicAdd(&bcur[hb[k]], 1);
            bpt[bp] = (unsigned short)j;
        }
    }
    __syncthreads();

    // ---------- edge build for MY quarter only ----------
    for (int p = tid; p < N_Q; p += NTHREADS) {
        int i = cidx[p];
        if ((i >> 10) != rank) continue;
        unsigned long long kj = ckey[p];
        if (!(kj >> 32)) continue;            // invalid
        float2 pj = cxy[p];
        int cell = ccell[p];
        int cx = cell & 63, cy = cell >> 6;
        int x0 = max(cx - 1, 0), x1 = min(cx + 1, 63);
        int y0 = max(cy - 1, 0), y1 = min(cy + 1, 63);
        int lidx = i & (QTR - 1);
        int cnt = 0;
        for (int yy = y0; yy <= y1; yy++) {
            int rs = cstart[yy * 64 + x0];
            int re = cstart[yy * 64 + x1 + 1];
            for (int q = rs; q < re; q++) {
                unsigned long long ki = ckey[q];
                if (ki <= kj) continue;       // lower rank / invalid / self
                float2 pi = cxy[q];
                float dx = pi.x - pj.x, dy = pi.y - pj.y;
                if (dx * dx + dy * dy < D2_THRESH) {
                    if (cnt < NBR_CAP) nbr[lidx * NBR_CAP + cnt] = cidx[q];
                    cnt++;
                }
            }
        }
        if (cnt == 0) {
            stat[i] = 1;                      // no higher-ranked neighbor
        } else {
            nbrcnt[lidx] = (cnt > NBR_CAP) ? (unsigned char)OVF : (unsigned char)cnt;
            int w = atomicAdd(&s_wl, 1);
            wl[w] = (unsigned short)lidx;
        }
    }
    __syncthreads();
    const int nwl = s_wl;

    // initial stat exchange (edge-build results)
    {
        unsigned int* statw = (unsigned int*)stat;
        if (tid < 256) {
            unsigned int wv = statw[rank * 256 + tid];
            uint32_t a = smem_u32(&statw[rank * 256 + tid]);
            #pragma unroll
            for (int r = 0; r < CLUSTER; r++)
                if (r != rank) st_cl_u32(mapa_rank(a, r), wv);
        }
    }
    CLUSTER_SYNC();

    // ---------- fixed-point rounds with per-round stat exchange ----------
    while (true) {
        if (tid == 0) s_my = 0;
        __syncthreads();
        int lu = 0;
        for (int w = tid; w < nwl; w += NTHREADS) {
            int lidx = wl[w];
            int i = rank * QTR + lidx;
            if (stat[i] != 0) continue;
            int c = nbrcnt[lidx];
            bool sup = false, pend = false;
            if (c != OVF) {
                #pragma unroll 1
                for (int k = 0; k < c; k++) {
                    unsigned char st = stat[nbr[lidx * NBR_CAP + k]];
                    if (st == 1) { sup = true; break; }
                    if (st == 0) pend = true;
                }
            } else {
                float s = iscore[i];
                unsigned long long kj = mk_key(s, i);
                float2 pj = ixy[i];
                int cx = min(63, max(0, (int)(pj.x * 0.125f)));
                int cy = min(63, max(0, (int)(pj.y * 0.125f)));
                int x0 = max(cx - 1, 0), x1 = min(cx + 1, 63);
                int y0 = max(cy - 1, 0), y1 = min(cy + 1, 63);
                for (int yy = y0; yy <= y1 && !sup; yy++) {
                    int rs = cstart[yy * 64 + x0];
                    int re = cstart[yy * 64 + x1 + 1];
                    for (int q = rs; q < re; q++) {
                        unsigned long long ki = ckey[q];
                        if (ki <= kj) continue;
                        float2 pi = cxy[q];
                        float dx = pi.x - pj.x, dy = pi.y - pj.y;
                        if (dx * dx + dy * dy < D2_THRESH) {
                            unsigned char st = stat[cidx[q]];
                            if (st == 1) { sup = true; break; }
                            if (st == 0) pend = true;
                        }
                    }
                }
            }
            if (sup)        stat[i] = 2;
            else if (!pend) stat[i] = 1;
            else            lu++;
        }
        if (lu) atomicAdd(&s_my, lu);
        __syncthreads();
        // exchange my stat quarter + my pending count
        {
            unsigned int* statw = (unsigned int*)stat;
            if (tid < 256) {
                unsigned int wv = statw[rank * 256 + tid];
                uint32_t a = smem_u32(&statw[rank * 256 + tid]);
                #pragma unroll
                for (int r = 0; r < CLUSTER; r++)
                    if (r != rank) st_cl_u32(mapa_rank(a, r), wv);
            }
            if (tid == 0) {
                int m = s_my;
                s_cnt[rank] = m;
                uint32_t a = smem_u32(&s_cnt[rank]);
                #pragma unroll
                for (int r = 0; r < CLUSTER; r++)
                    if (r != rank) st_cl_u32(mapa_rank(a, r), m);
            }
        }
        CLUSTER_SYNC();
        if (s_cnt[0] + s_cnt[1] + s_cnt[2] + s_cnt[3] == 0) break;
    }

    // ---------- rank MY quarter's retained points, scatter to output ----------
    {
        const int nvalid = bstart[N_Q];
        int i = rank * QTR + tid;
        if (stat[i] == 1) {
            float s = iscore[i];
            unsigned long long kj = mk_key(s, i);
            int b = min(4095, (int)(s * 4096.0f));
            int r = nvalid - bstart[b + 1];
            int e = bstart[b + 1];
            for (int q = bstart[b]; q < e; q++) {
                int idx2 = bpt[q];
                if (mk_key(iscore[idx2], idx2) > kj) r++;
            }
            out[5 * r + 3 + cls] = s;
        }
    }
}

extern "C" void kernel_launch(void* const* d_in, const int* in_sizes, int n_in,
                              void* d_out, int out_size) {
    const float* logits = (const float*)d_in[0];   // [1,4096,3]
    const float* boxes  = (const float*)d_in[1];   // [1,4096,2]
    // d_in[2] = pred_gids (unused by reference)
    const float* ts     = (const float*)d_in[3];   // [1,2] = (w,h)
    float* out = (float*)d_out;                    // [1,4096,5]

    cudaFuncSetAttribute(nms_kernel,
                         cudaFuncAttributeMaxDynamicSharedMemorySize, SMEM_BYTES);
    nms_kernel<<<2 * CLUSTER, NTHREADS, SMEM_BYTES>>>(logits, boxes, ts, out);
}